// round 1
// baseline (speedup 1.0000x reference)
#include <cuda_runtime.h>

// Problem constants (fixed shapes per setup_inputs)
constexpr int NBATCH = 16;
constexpr int NANCH  = 4;
constexpr int NT     = 64;     // targets per image
constexpr int NGH    = 76;
constexpr int NGW    = 136;
constexpr int GRID   = NGH * NGW;          // 10336
constexpr int CELLS  = NANCH * GRID;       // 41344 cells per batch
constexpr int NBC    = NBATCH * CELLS;     // 661504

// stride = img_w / nGw = 1088 / 136 = 8.0 exactly
constexpr float INV_STRIDE = 0.125f;

__device__ int g_has_fg[NBATCH];

__global__ void reset_flags_kernel() {
    int i = threadIdx.x;
    if (i < NBATCH) g_has_fg[i] = 0;
}

__global__ void assign_kernel(const float* __restrict__ targets,
                              const float* __restrict__ anchors,
                              float* __restrict__ out)
{
    __shared__ float sminx[NT], sminy[NT], smaxx[NT], smaxy[NT];
    __shared__ float sarea[NT];
    __shared__ float sgx[NT], sgy[NT], sgw[NT], sgh[NT], stid[NT];

    const int b   = blockIdx.y;
    const int tix = threadIdx.x;

    // ---- load + preprocess the 64 GT boxes for this batch into shared ----
    if (tix < NT) {
        const float* t = targets + (b * NT + tix) * 6;
        float tx = t[2], ty = t[3], tw = t[4], th = t[5];
        // gxy = clip(t[2:4]*scale, 0, scale-1); gwh = t[4:6]*scale
        float gx = fminf(fmaxf(tx * (float)NGW, 0.0f), (float)NGW - 1.0f);
        float gy = fminf(fmaxf(ty * (float)NGH, 0.0f), (float)NGH - 1.0f);
        float gw = tw * (float)NGW;
        float gh = th * (float)NGH;
        sgx[tix] = gx;  sgy[tix] = gy;
        sgw[tix] = gw;  sgh[tix] = gh;
        sminx[tix] = gx - gw * 0.5f;
        smaxx[tix] = gx + gw * 0.5f;
        sminy[tix] = gy - gh * 0.5f;
        smaxy[tix] = gy + gh * 0.5f;
        sarea[tix] = gw * gh;
        stid[tix]  = t[1];
    }
    __syncthreads();

    const int c = blockIdx.x * blockDim.x + tix;
    if (c >= CELLS) return;

    // cell -> (anchor, gy, gx)
    const int a   = c / GRID;
    const int r   = c - a * GRID;
    const int gyi = r / NGW;
    const int gxi = r - gyi * NGW;

    const float aw = anchors[2 * a]     * INV_STRIDE;
    const float ah = anchors[2 * a + 1] * INV_STRIDE;
    const float px = (float)gxi;
    const float py = (float)gyi;

    const float b1minx = px - aw * 0.5f;
    const float b1maxx = px + aw * 0.5f;
    const float b1miny = py - ah * 0.5f;
    const float b1maxy = py + ah * 0.5f;
    const float a1     = aw * ah;

    float best = -1.0f;
    int   bt   = 0;

    #pragma unroll 8
    for (int t = 0; t < NT; t++) {
        float dx = fminf(b1maxx, smaxx[t]) - fmaxf(b1minx, sminx[t]);
        float dy = fminf(b1maxy, smaxy[t]) - fmaxf(b1miny, sminy[t]);
        dx = fmaxf(dx, 0.0f);
        dy = fmaxf(dy, 0.0f);
        float inter = dx * dy;
        // match reference op order: a1 + a2 - inter + 1e-16
        float iou = inter / (a1 + sarea[t] - inter + 1e-16f);
        if (iou > best) { best = iou; bt = t; }  // strict > : first-max, matches argmax
    }

    const bool fg = best > 0.5f;
    float conf;
    if (fg)                                   conf =  1.0f;
    else if (best > 0.4f && best < 0.5f)      conf = -1.0f;
    else                                      conf =  0.0f;

    float4 box = make_float4(0.0f, 0.0f, 0.0f, 0.0f);
    float  tidv = -1.0f;
    if (fg) {
        box.x = (sgx[bt] - px) / aw;
        box.y = (sgy[bt] - py) / ah;
        box.z = logf(sgw[bt] / aw);
        box.w = logf(sgh[bt] / ah);
        tidv  = stid[bt];
        atomicOr(&g_has_fg[b], 1);
    }

    const int base = b * CELLS + c;
    out[base] = conf;                                  // tconf
    reinterpret_cast<float4*>(out + NBC)[base] = box;  // tbox (aligned: NBC % 4 == 0)
    out[NBC * 5 + base] = tidv;                        // tid
}

// If a batch has no foreground cell at all, every tid in it must be -1.
__global__ void fixup_tid_kernel(float* __restrict__ out)
{
    int idx = blockIdx.x * blockDim.x + threadIdx.x;
    if (idx >= NBC) return;
    int b = idx / CELLS;
    if (g_has_fg[b] == 0) out[NBC * 5 + idx] = -1.0f;
}

extern "C" void kernel_launch(void* const* d_in, const int* in_sizes, int n_in,
                              void* d_out, int out_size)
{
    // d_in[0] = p_cat (unused, shape-only), d_in[1] = targets, d_in[2] = anchors,
    // d_in[3] = img_w, d_in[4] = img_h (both fixed; stride hardcoded = 8)
    const float* targets = (const float*)d_in[1];
    const float* anchors = (const float*)d_in[2];
    float* out = (float*)d_out;

    reset_flags_kernel<<<1, 32>>>();

    dim3 grid((CELLS + 255) / 256, NBATCH);
    assign_kernel<<<grid, 256>>>(targets, anchors, out);

    fixup_tid_kernel<<<(NBC + 255) / 256, 256>>>(out);
}

// round 3
// speedup vs baseline: 3.7842x; 3.7842x over previous
#include <cuda_runtime.h>

// Fixed problem shapes (per setup_inputs)
constexpr int NBATCH = 16;
constexpr int NANCH  = 4;
constexpr int NT     = 64;
constexpr int NGH    = 76;
constexpr int NGW    = 136;
constexpr int GRID   = NGH * NGW;        // 10336
constexpr int CELLS  = NANCH * GRID;     // 41344
constexpr int NBC    = NBATCH * CELLS;   // 661504

// stride = 1088/136 = 8.0 exactly
constexpr float INV_STRIDE = 0.125f;

constexpr int TPB = 512;
constexpr int WX  = 68;                  // x-tile width (136 = 2 * 68)
constexpr int TILE_CELLS = WX * NGH;     // 5168 cells per block

__global__ __launch_bounds__(TPB) void assign_kernel(
    const float* __restrict__ targets,
    const float* __restrict__ anchors,
    float* __restrict__ out)
{
    // 38.4 KB static shared — under the 48 KB limit, no attribute call needed.
    __shared__ float dxtab[NT * WX];     // 4352 floats
    __shared__ float dytab[NT * NGH];    // 4864 floats
    __shared__ float sS[NT];
    __shared__ float sgx[NT], sgy[NT], sgw[NT], sgh[NT], stid[NT];

    const int xt = blockIdx.x;           // 0 or 1: x-tile
    const int a  = blockIdx.y;
    const int b  = blockIdx.z;
    const int tx = threadIdx.x;
    const int x0 = xt * WX;

    const float aw  = __ldg(&anchors[2 * a])     * INV_STRIDE;
    const float ah  = __ldg(&anchors[2 * a + 1]) * INV_STRIDE;
    const float aw2 = aw * 0.5f;
    const float ah2 = ah * 0.5f;
    const float a1  = aw * ah;

    // ---- per-target preprocessing ----
    if (tx < NT) {
        const float* t = targets + (b * NT + tx) * 6;
        float gx = fminf(fmaxf(t[2] * (float)NGW, 0.0f), (float)NGW - 1.0f);
        float gy = fminf(fmaxf(t[3] * (float)NGH, 0.0f), (float)NGH - 1.0f);
        float gw = t[4] * (float)NGW;
        float gh = t[5] * (float)NGH;
        sgx[tx] = gx; sgy[tx] = gy; sgw[tx] = gw; sgh[tx] = gh;
        sS[tx]  = a1 + gw * gh;          // a1 + a2, reference add order
        stid[tx] = t[1];
    }
    __syncthreads();

    // ---- separable intersection tables for this x-tile ----
    // dxtab[t][px_local] = max(0, min(px+aw2, gx+gw/2) - max(px-aw2, gx-gw/2))
    for (int i = tx; i < NT * WX; i += TPB) {
        int t  = i / WX;
        int px = i - t * WX + x0;
        float fpx = (float)px;
        float hi = fminf(fpx + aw2, sgx[t] + sgw[t] * 0.5f);
        float lo = fmaxf(fpx - aw2, sgx[t] - sgw[t] * 0.5f);
        dxtab[i] = fmaxf(hi - lo, 0.0f);
    }
    for (int i = tx; i < NT * NGH; i += TPB) {
        int t  = i / NGH;
        int py = i - t * NGH;
        float fpy = (float)py;
        float hi = fminf(fpy + ah2, sgy[t] + sgh[t] * 0.5f);
        float lo = fmaxf(fpy - ah2, sgy[t] - sgh[t] * 0.5f);
        dytab[i] = fmaxf(hi - lo, 0.0f);
    }
    __syncthreads();

    // ---- main assignment loop over this block's tile ----
    for (int idx = tx; idx < TILE_CELLS; idx += TPB) {
        const int gyi = idx / WX;
        const int xl  = idx - gyi * WX;   // local x in tile
        const int gxi = x0 + xl;

        // argmax_t of inter_t / (s_t - inter_t + eps) via cross-multiplied
        // comparison: inter_t * s_best > inter_best * s_t
        // (inter*inter terms cancel exactly; strict > keeps first max,
        //  matching jnp.argmax tie-breaking for the common zero-overlap case)
        float bi = dxtab[xl] * dytab[gyi];
        float bs = sS[0];
        int   bt = 0;
        #pragma unroll
        for (int t = 1; t < NT; t++) {
            float inter = dxtab[t * WX + xl] * dytab[t * NGH + gyi];
            float st    = sS[t];
            bool p = inter * bs > bi * st;
            bi = p ? inter : bi;
            bs = p ? st    : bs;
            bt = p ? t     : bt;
        }

        // exact rounded IoU for thresholding, matching reference:
        // iou = inter / ((a1+a2) - inter + 1e-16)
        float u = (bs - bi) + 1e-16f;
        float iou_max = __fdiv_rn(bi, u);

        const bool fg = iou_max > 0.5f;
        float conf;
        if (fg)                                      conf =  1.0f;
        else if (iou_max > 0.4f && iou_max < 0.5f)   conf = -1.0f;
        else                                         conf =  0.0f;

        float4 box = make_float4(0.0f, 0.0f, 0.0f, 0.0f);
        float tidv = -1.0f;
        if (fg) {
            float px = (float)gxi, py = (float)gyi;
            box.x = __fdiv_rn(sgx[bt] - px, aw);
            box.y = __fdiv_rn(sgy[bt] - py, ah);
            box.z = logf(__fdiv_rn(sgw[bt], aw));
            box.w = logf(__fdiv_rn(sgh[bt], ah));
            tidv  = stid[bt];
            // NOTE: has_fg in the reference is a no-op: tid = where(fg & any(fg))
            // and fg implies any(fg), so no cross-cell pass is needed.
        }

        const int base = b * CELLS + a * GRID + gyi * NGW + gxi;
        out[base] = conf;                                   // tconf
        reinterpret_cast<float4*>(out + NBC)[base] = box;   // tbox
        out[NBC * 5 + base] = tidv;                         // tid
    }
}

extern "C" void kernel_launch(void* const* d_in, const int* in_sizes, int n_in,
                              void* d_out, int out_size)
{
    // d_in[0]=p_cat (unused, shape-only), d_in[1]=targets, d_in[2]=anchors,
    // d_in[3,4]=img_w/h (fixed 1088x608; stride hardcoded = 8)
    const float* targets = (const float*)d_in[1];
    const float* anchors = (const float*)d_in[2];
    float* out = (float*)d_out;

    dim3 grid(NGW / WX, NANCH, NBATCH);   // (2, 4, 16) = 128 blocks
    assign_kernel<<<grid, TPB>>>(targets, anchors, out);
}

// round 4
// speedup vs baseline: 4.1153x; 1.0875x over previous
#include <cuda_runtime.h>

// Fixed problem shapes (per setup_inputs)
constexpr int NBATCH = 16;
constexpr int NANCH  = 4;
constexpr int NT     = 64;
constexpr int NGH    = 76;
constexpr int NGW    = 136;
constexpr int GRID   = NGH * NGW;        // 10336
constexpr int CELLS  = NANCH * GRID;     // 41344
constexpr int NBC    = NBATCH * CELLS;   // 661504

// stride = 1088/136 = 8.0 exactly
constexpr float INV_STRIDE = 0.125f;

constexpr int TPB = 256;
constexpr int WX  = 68;                  // x-tile width (136 = 2*68)
constexpr int QPR = WX / 4;              // 17 quads per row
constexpr int YT  = 38;                  // rows per y-tile (76 = 2*38)
constexpr int QUADS = QPR * YT;          // 646 quads per block

__global__ __launch_bounds__(TPB) void assign_kernel(
    const float* __restrict__ targets,
    const float* __restrict__ anchors,
    float* __restrict__ out)
{
    // ~28.3 KB static shared
    __shared__ float qxtab[NT * WX];     // dx / s  (normalized x-overlap)
    __shared__ float dytab[NT * YT];     // dy for this y-tile
    __shared__ float sS[NT];             // s = a1 + a2 (reference add order)
    __shared__ float rsS[NT];            // 1/s
    __shared__ float sgx[NT], sgy[NT], sgw[NT], sgh[NT], stid[NT];

    const int xt = blockIdx.x & 1;
    const int yt = blockIdx.x >> 1;
    const int a  = blockIdx.y;
    const int b  = blockIdx.z;
    const int tx = threadIdx.x;
    const int x0 = xt * WX;
    const int y0 = yt * YT;

    const float aw  = __ldg(&anchors[2 * a])     * INV_STRIDE;
    const float ah  = __ldg(&anchors[2 * a + 1]) * INV_STRIDE;
    const float aw2 = aw * 0.5f;
    const float ah2 = ah * 0.5f;
    const float a1  = aw * ah;

    // ---- per-target preprocessing ----
    if (tx < NT) {
        const float* t = targets + (b * NT + tx) * 6;
        float gx = fminf(fmaxf(t[2] * (float)NGW, 0.0f), (float)NGW - 1.0f);
        float gy = fminf(fmaxf(t[3] * (float)NGH, 0.0f), (float)NGH - 1.0f);
        float gw = t[4] * (float)NGW;
        float gh = t[5] * (float)NGH;
        sgx[tx] = gx; sgy[tx] = gy; sgw[tx] = gw; sgh[tx] = gh;
        float s = a1 + gw * gh;
        sS[tx]  = s;
        rsS[tx] = __fdiv_rn(1.0f, s);
        stid[tx] = t[1];
    }
    __syncthreads();

    // ---- normalized separable overlap tables for this tile ----
    for (int i = tx; i < NT * WX; i += TPB) {
        int t  = i / WX;
        int px = i - t * WX + x0;
        float fpx = (float)px;
        float hi = fminf(fpx + aw2, sgx[t] + sgw[t] * 0.5f);
        float lo = fmaxf(fpx - aw2, sgx[t] - sgw[t] * 0.5f);
        qxtab[i] = fmaxf(hi - lo, 0.0f) * rsS[t];
    }
    for (int i = tx; i < NT * YT; i += TPB) {
        int t  = i / YT;
        int py = i - t * YT + y0;
        float fpy = (float)py;
        float hi = fminf(fpy + ah2, sgy[t] + sgh[t] * 0.5f);
        float lo = fmaxf(fpy - ah2, sgy[t] - sgh[t] * 0.5f);
        dytab[i] = fmaxf(hi - lo, 0.0f);
    }
    __syncthreads();

    // ---- main loop: 4 cells (one x-quad) per thread-iteration ----
    for (int q = tx; q < QUADS; q += TPB) {
        const int row = q / QPR;
        const int xq  = q - row * QPR;
        const int xl  = xq * 4;
        const int gyi = y0 + row;

        // argmax_t of key = (dx_t/s_t) * dy_t  (== argmax of iou; iou is
        // strictly increasing in inter/s). keys >= 0; init -1 so t=0 always
        // claims first, matching argmax first-max tie-breaking.
        float bk[4] = {-1.0f, -1.0f, -1.0f, -1.0f};
        int   bt[4] = {0, 0, 0, 0};

        #pragma unroll
        for (int t = 0; t < NT; t++) {
            const float4 q4 = *reinterpret_cast<const float4*>(&qxtab[t * WX + xl]);
            const float  dv = dytab[t * YT + row];
            float k0 = q4.x * dv, k1 = q4.y * dv, k2 = q4.z * dv, k3 = q4.w * dv;
            if (k0 > bk[0]) { bk[0] = k0; bt[0] = t; }
            if (k1 > bk[1]) { bk[1] = k1; bt[1] = t; }
            if (k2 > bk[2]) { bk[2] = k2; bt[2] = t; }
            if (k3 > bk[3]) { bk[3] = k3; bt[3] = t; }
        }

        // ---- epilogue: exact recompute of inter & iou for the winner ----
        const float py = (float)gyi;
        float4 conf4, tid4;
        float4 box[4];
        float* confp = &conf4.x;
        float* tidp  = &tid4.x;

        #pragma unroll
        for (int j = 0; j < 4; j++) {
            const int t = bt[j];
            const float gx = sgx[t], gy = sgy[t], gw = sgw[t], gh = sgh[t];
            const float s  = sS[t];
            const float pxf = (float)(x0 + xl + j);
            float dx = fmaxf(fminf(pxf + aw2, gx + gw * 0.5f)
                           - fmaxf(pxf - aw2, gx - gw * 0.5f), 0.0f);
            float dyv = fmaxf(fminf(py + ah2, gy + gh * 0.5f)
                            - fmaxf(py - ah2, gy - gh * 0.5f), 0.0f);
            float inter = dx * dyv;
            float iou = __fdiv_rn(inter, (s - inter) + 1e-16f);

            const bool fg = iou > 0.5f;
            confp[j] = fg ? 1.0f : ((iou > 0.4f && iou < 0.5f) ? -1.0f : 0.0f);

            float4 bx = make_float4(0.0f, 0.0f, 0.0f, 0.0f);
            float tv = -1.0f;
            if (fg) {
                bx.x = __fdiv_rn(gx - pxf, aw);
                bx.y = __fdiv_rn(gy - py,  ah);
                bx.z = logf(__fdiv_rn(gw, aw));
                bx.w = logf(__fdiv_rn(gh, ah));
                tv   = stid[t];
                // has_fg in the reference is a no-op (fg implies any(fg)).
            }
            box[j] = bx;
            tidp[j] = tv;
        }

        const int base = b * CELLS + a * GRID + gyi * NGW + x0 + xl; // %4 == 0
        *reinterpret_cast<float4*>(out + base) = conf4;              // tconf
        float4* tb = reinterpret_cast<float4*>(out + NBC) + base;    // tbox
        tb[0] = box[0]; tb[1] = box[1]; tb[2] = box[2]; tb[3] = box[3];
        *reinterpret_cast<float4*>(out + NBC * 5 + base) = tid4;     // tid
    }
}

extern "C" void kernel_launch(void* const* d_in, const int* in_sizes, int n_in,
                              void* d_out, int out_size)
{
    // d_in[0]=p_cat (unused, shape-only), d_in[1]=targets, d_in[2]=anchors,
    // d_in[3,4]=img_w/h (fixed 1088x608; stride hardcoded = 8)
    const float* targets = (const float*)d_in[1];
    const float* anchors = (const float*)d_in[2];
    float* out = (float*)d_out;

    dim3 grid(4, NANCH, NBATCH);   // (2 x-tiles * 2 y-tiles, 4, 16) = 256 blocks
    assign_kernel<<<grid, TPB>>>(targets, anchors, out);
}

// round 5
// speedup vs baseline: 4.9466x; 1.2020x over previous
#include <cuda_runtime.h>

// Fixed problem shapes (per setup_inputs)
constexpr int NBATCH = 16;
constexpr int NANCH  = 4;
constexpr int NT     = 64;
constexpr int NGH    = 76;
constexpr int NGW    = 136;
constexpr int GRID   = NGH * NGW;        // 10336
constexpr int CELLS  = NANCH * GRID;     // 41344
constexpr int NBC    = NBATCH * CELLS;   // 661504

// stride = 1088/136 = 8.0 exactly
constexpr float INV_STRIDE = 0.125f;

constexpr int TPB = 256;
constexpr int WX  = 68;                  // x-tile width  (136 = 2*68)
constexpr int QPR = WX / 4;              // 17 quads per row
constexpr int YT  = 19;                  // rows per y-tile (76 = 4*19)
constexpr int QUADS = QPR * YT;          // 323 quads per block

__global__ __launch_bounds__(TPB) void assign_kernel(
    const float* __restrict__ targets,
    const float* __restrict__ anchors,
    float* __restrict__ out)
{
    // ~29 KB static shared
    __shared__ float qxtab[NT * WX];     // dx/s (normalized x-overlap)
    __shared__ float sdy[YT * NT];       // compacted dy per row
    __shared__ int   stl[YT * NT];       // compacted target index per row
    __shared__ int   scnt[YT];           // active-target count per row
    __shared__ float sS[NT];             // s = a1 + a2 (reference add order)
    __shared__ float rsS[NT];            // 1/s
    __shared__ float sgx[NT], sgy[NT], sgw[NT], sgh[NT], stid[NT];

    const int xt = blockIdx.x & 1;       // 0..1
    const int yt = blockIdx.x >> 1;      // 0..3
    const int a  = blockIdx.y;
    const int b  = blockIdx.z;
    const int tx = threadIdx.x;
    const int x0 = xt * WX;
    const int y0 = yt * YT;

    const float aw  = __ldg(&anchors[2 * a])     * INV_STRIDE;
    const float ah  = __ldg(&anchors[2 * a + 1]) * INV_STRIDE;
    const float aw2 = aw * 0.5f;
    const float ah2 = ah * 0.5f;
    const float a1  = aw * ah;

    // ---- per-target preprocessing ----
    if (tx < NT) {
        const float* t = targets + (b * NT + tx) * 6;
        float gx = fminf(fmaxf(t[2] * (float)NGW, 0.0f), (float)NGW - 1.0f);
        float gy = fminf(fmaxf(t[3] * (float)NGH, 0.0f), (float)NGH - 1.0f);
        float gw = t[4] * (float)NGW;
        float gh = t[5] * (float)NGH;
        sgx[tx] = gx; sgy[tx] = gy; sgw[tx] = gw; sgh[tx] = gh;
        float s = a1 + gw * gh;
        sS[tx]  = s;
        rsS[tx] = __fdiv_rn(1.0f, s);
        stid[tx] = t[1];
    }
    __syncthreads();

    // ---- normalized x-overlap table for this x-tile ----
    for (int i = tx; i < NT * WX; i += TPB) {
        int t  = i / WX;
        int px = i - t * WX + x0;
        float fpx = (float)px;
        float hi = fminf(fpx + aw2, sgx[t] + sgw[t] * 0.5f);
        float lo = fmaxf(fpx - aw2, sgx[t] - sgw[t] * 0.5f);
        qxtab[i] = fmaxf(hi - lo, 0.0f) * rsS[t];
    }

    // ---- per-row compacted active-target lists (dy > 0) ----
    // Pruned targets have key == 0. If every key at a cell is 0 the outputs
    // are winner-independent (iou=0 -> conf=0, box=0, tid=-1), so pruning
    // preserves the reference result; list is built in ascending t, keeping
    // argmax first-max tie order for positive keys.
    if (tx < YT) {
        const float fpy = (float)(y0 + tx);
        int c = 0;
        for (int t = 0; t < NT; t++) {
            float hi = fminf(fpy + ah2, sgy[t] + sgh[t] * 0.5f);
            float lo = fmaxf(fpy - ah2, sgy[t] - sgh[t] * 0.5f);
            float d  = hi - lo;
            if (d > 0.0f) {
                stl[tx * NT + c] = t;
                sdy[tx * NT + c] = d;
                c++;
            }
        }
        scnt[tx] = c;
    }
    __syncthreads();

    const float4* qx4 = reinterpret_cast<const float4*>(qxtab);

    // ---- main loop: one x-quad per thread-iteration, pruned target list ----
    for (int q = tx; q < QUADS; q += TPB) {
        const int row = q / QPR;
        const int xq  = q - row * QPR;
        const int xl  = xq * 4;
        const int gyi = y0 + row;

        // argmax_t of key = (dx_t/s_t)*dy_t  (== argmax iou: monotone map)
        float bk0 = 0.0f, bk1 = 0.0f, bk2 = 0.0f, bk3 = 0.0f;
        int   bt0 = 0,    bt1 = 0,    bt2 = 0,    bt3 = 0;

        const int cnt = scnt[row];
        for (int e = 0; e < cnt; e++) {
            const int   t  = stl[row * NT + e];
            const float dv = sdy[row * NT + e];
            const float4 q4 = qx4[t * QPR + xq];
            float k0 = q4.x * dv, k1 = q4.y * dv, k2 = q4.z * dv, k3 = q4.w * dv;
            if (k0 > bk0) { bk0 = k0; bt0 = t; }
            if (k1 > bk1) { bk1 = k1; bt1 = t; }
            if (k2 > bk2) { bk2 = k2; bt2 = t; }
            if (k3 > bk3) { bk3 = k3; bt3 = t; }
        }

        // ---- epilogue: exact recompute of inter & iou for each winner ----
        const float py = (float)gyi;
        int bt[4] = {bt0, bt1, bt2, bt3};
        float4 conf4, tid4;
        float4 box[4];
        float* confp = &conf4.x;
        float* tidp  = &tid4.x;

        #pragma unroll
        for (int j = 0; j < 4; j++) {
            const int t = bt[j];
            const float gx = sgx[t], gy = sgy[t], gw = sgw[t], gh = sgh[t];
            const float s  = sS[t];
            const float pxf = (float)(x0 + xl + j);
            float dx = fmaxf(fminf(pxf + aw2, gx + gw * 0.5f)
                           - fmaxf(pxf - aw2, gx - gw * 0.5f), 0.0f);
            float dyv = fmaxf(fminf(py + ah2, gy + gh * 0.5f)
                            - fmaxf(py - ah2, gy - gh * 0.5f), 0.0f);
            float inter = dx * dyv;
            float iou = __fdiv_rn(inter, (s - inter) + 1e-16f);

            const bool fg = iou > 0.5f;
            confp[j] = fg ? 1.0f : ((iou > 0.4f && iou < 0.5f) ? -1.0f : 0.0f);

            float4 bx = make_float4(0.0f, 0.0f, 0.0f, 0.0f);
            float tv = -1.0f;
            if (fg) {
                bx.x = __fdiv_rn(gx - pxf, aw);
                bx.y = __fdiv_rn(gy - py,  ah);
                bx.z = logf(__fdiv_rn(gw, aw));
                bx.w = logf(__fdiv_rn(gh, ah));
                tv   = stid[t];
                // has_fg in the reference is a no-op (fg implies any(fg)).
            }
            box[j] = bx;
            tidp[j] = tv;
        }

        const int base = b * CELLS + a * GRID + gyi * NGW + x0 + xl; // %4 == 0
        *reinterpret_cast<float4*>(out + base) = conf4;              // tconf
        float4* tb = reinterpret_cast<float4*>(out + NBC) + base;    // tbox
        tb[0] = box[0]; tb[1] = box[1]; tb[2] = box[2]; tb[3] = box[3];
        *reinterpret_cast<float4*>(out + NBC * 5 + base) = tid4;     // tid
    }
}

extern "C" void kernel_launch(void* const* d_in, const int* in_sizes, int n_in,
                              void* d_out, int out_size)
{
    // d_in[0]=p_cat (unused, shape-only), d_in[1]=targets, d_in[2]=anchors,
    // d_in[3,4]=img_w/h (fixed 1088x608; stride hardcoded = 8)
    const float* targets = (const float*)d_in[1];
    const float* anchors = (const float*)d_in[2];
    float* out = (float*)d_out;

    dim3 grid(8, NANCH, NBATCH);   // (2 x-tiles * 4 y-tiles, 4, 16) = 512 blocks
    assign_kernel<<<grid, TPB>>>(targets, anchors, out);
}

// round 6
// speedup vs baseline: 5.6117x; 1.1345x over previous
#include <cuda_runtime.h>

// Fixed problem shapes (per setup_inputs)
constexpr int NBATCH = 16;
constexpr int NANCH  = 4;
constexpr int NT     = 64;
constexpr int NGH    = 76;
constexpr int NGW    = 136;
constexpr int GRID   = NGH * NGW;        // 10336
constexpr int CELLS  = NANCH * GRID;     // 41344
constexpr int NBC    = NBATCH * CELLS;   // 661504

// stride = 1088/136 = 8.0 exactly
constexpr float INV_STRIDE = 0.125f;

constexpr int TPB = 352;                 // 11 warps; >= QUADS so one quad/thread
constexpr int WX  = 68;                  // x-tile width  (136 = 2*68)
constexpr int QPR = WX / 4;              // 17 quads per row
constexpr int YT  = 19;                  // rows per y-tile (76 = 4*19)
constexpr int QUADS = QPR * YT;          // 323 quads per block

__global__ __launch_bounds__(TPB) void assign_kernel(
    const float* __restrict__ targets,
    const float* __restrict__ anchors,
    float* __restrict__ out)
{
    // ~24 KB static shared
    __shared__ float    qxtab[NT * WX];  // dx/s (normalized x-overlap), [t][x]
    __shared__ float    sdy[YT * NT];    // dense dy per (row, t)
    __shared__ unsigned smask[YT * 2];   // per-row active-target bitmask (2x u32)
    __shared__ float sS[NT];             // s = a1 + a2 (reference add order)
    __shared__ float rsS[NT];            // 1/s
    __shared__ float sgx[NT], sgy[NT], sgw[NT], sgh[NT], stid[NT];

    const int xt = blockIdx.x & 1;       // 0..1
    const int yt = blockIdx.x >> 1;      // 0..3
    const int a  = blockIdx.y;
    const int b  = blockIdx.z;
    const int tx = threadIdx.x;
    const int x0 = xt * WX;
    const int y0 = yt * YT;

    const float aw  = __ldg(&anchors[2 * a])     * INV_STRIDE;
    const float ah  = __ldg(&anchors[2 * a + 1]) * INV_STRIDE;
    const float aw2 = aw * 0.5f;
    const float ah2 = ah * 0.5f;
    const float a1  = aw * ah;

    // ---- phase 1: per-target preprocessing (64 threads, independent) ----
    if (tx < NT) {
        const float* t = targets + (b * NT + tx) * 6;
        float gx = fminf(fmaxf(t[2] * (float)NGW, 0.0f), (float)NGW - 1.0f);
        float gy = fminf(fmaxf(t[3] * (float)NGH, 0.0f), (float)NGH - 1.0f);
        float gw = t[4] * (float)NGW;
        float gh = t[5] * (float)NGH;
        sgx[tx] = gx; sgy[tx] = gy; sgw[tx] = gw; sgh[tx] = gh;
        float s = a1 + gw * gh;
        sS[tx]  = s;
        rsS[tx] = __fdiv_rn(1.0f, s);
        stid[tx] = t[1];
    }
    __syncthreads();

    // ---- phase 2a: normalized x-overlap table for this x-tile ----
    for (int i = tx; i < NT * WX; i += TPB) {
        int t  = i / WX;
        int px = i - t * WX + x0;
        float fpx = (float)px;
        float hi = fminf(fpx + aw2, sgx[t] + sgw[t] * 0.5f);
        float lo = fmaxf(fpx - aw2, sgx[t] - sgw[t] * 0.5f);
        qxtab[i] = fmaxf(hi - lo, 0.0f) * rsS[t];
    }

    // ---- phase 2b: dense dy + per-row bitmask (ballot, fully parallel) ----
    // bit `lane` of smask[row*2 + half] marks t = half*32 + lane active (dy>0).
    // Pruned targets have key == 0; when all keys are 0 the outputs are
    // winner-independent (exact epilogue recompute gives iou=0 -> conf=0,
    // box=0, tid=-1), so pruning preserves the reference result. Bit
    // iteration is ascending in t, keeping argmax first-max tie order.
    {
        const int warp = tx >> 5;
        const int lane = tx & 31;
        for (int p = warp; p < YT * 2; p += TPB / 32) {
            const int row  = p >> 1;
            const int t    = ((p & 1) << 5) | lane;
            const float fpy = (float)(y0 + row);
            float hi = fminf(fpy + ah2, sgy[t] + sgh[t] * 0.5f);
            float lo = fmaxf(fpy - ah2, sgy[t] - sgh[t] * 0.5f);
            float d  = hi - lo;
            sdy[row * NT + t] = d;
            unsigned m = __ballot_sync(0xffffffffu, d > 0.0f);
            if (lane == 0) smask[p] = m;
        }
    }
    __syncthreads();

    // ---- main: exactly one x-quad per thread ----
    if (tx < QUADS) {
        const int row = tx / QPR;
        const int xq  = tx - row * QPR;
        const int xl  = xq * 4;
        const int gyi = y0 + row;

        const float4* qx4  = reinterpret_cast<const float4*>(qxtab);
        const float*  dyr  = &sdy[row * NT];

        // argmax_t of key = (dx_t/s_t)*dy_t (== argmax iou: monotone map)
        float bk0 = 0.0f, bk1 = 0.0f, bk2 = 0.0f, bk3 = 0.0f;
        int   bt0 = 0,    bt1 = 0,    bt2 = 0,    bt3 = 0;

        unsigned m0 = smask[row * 2];
        unsigned m1 = smask[row * 2 + 1];
        while (m0) {
            const int t = __ffs(m0) - 1;  m0 &= m0 - 1;
            const float dv = dyr[t];
            const float4 q4 = qx4[t * QPR + xq];
            float k0 = q4.x * dv, k1 = q4.y * dv, k2 = q4.z * dv, k3 = q4.w * dv;
            if (k0 > bk0) { bk0 = k0; bt0 = t; }
            if (k1 > bk1) { bk1 = k1; bt1 = t; }
            if (k2 > bk2) { bk2 = k2; bt2 = t; }
            if (k3 > bk3) { bk3 = k3; bt3 = t; }
        }
        while (m1) {
            const int t = __ffs(m1) + 31;  m1 &= m1 - 1;
            const float dv = dyr[t];
            const float4 q4 = qx4[t * QPR + xq];
            float k0 = q4.x * dv, k1 = q4.y * dv, k2 = q4.z * dv, k3 = q4.w * dv;
            if (k0 > bk0) { bk0 = k0; bt0 = t; }
            if (k1 > bk1) { bk1 = k1; bt1 = t; }
            if (k2 > bk2) { bk2 = k2; bt2 = t; }
            if (k3 > bk3) { bk3 = k3; bt3 = t; }
        }

        // ---- epilogue: exact recompute of inter & iou for each winner ----
        const float py = (float)gyi;
        int bt[4] = {bt0, bt1, bt2, bt3};
        float4 conf4, tid4;
        float4 box[4];
        float* confp = &conf4.x;
        float* tidp  = &tid4.x;

        #pragma unroll
        for (int j = 0; j < 4; j++) {
            const int t = bt[j];
            const float gx = sgx[t], gy = sgy[t], gw = sgw[t], gh = sgh[t];
            const float s  = sS[t];
            const float pxf = (float)(x0 + xl + j);
            float dx  = fmaxf(fminf(pxf + aw2, gx + gw * 0.5f)
                            - fmaxf(pxf - aw2, gx - gw * 0.5f), 0.0f);
            float dyv = fmaxf(fminf(py + ah2, gy + gh * 0.5f)
                            - fmaxf(py - ah2, gy - gh * 0.5f), 0.0f);
            float inter = dx * dyv;
            float iou = __fdiv_rn(inter, (s - inter) + 1e-16f);

            const bool fg = iou > 0.5f;
            confp[j] = fg ? 1.0f : ((iou > 0.4f && iou < 0.5f) ? -1.0f : 0.0f);

            float4 bx = make_float4(0.0f, 0.0f, 0.0f, 0.0f);
            float tv = -1.0f;
            if (fg) {
                bx.x = __fdiv_rn(gx - pxf, aw);
                bx.y = __fdiv_rn(gy - py,  ah);
                bx.z = logf(__fdiv_rn(gw, aw));
                bx.w = logf(__fdiv_rn(gh, ah));
                tv   = stid[t];
                // has_fg in the reference is a no-op (fg implies any(fg)).
            }
            box[j] = bx;
            tidp[j] = tv;
        }

        const int base = b * CELLS + a * GRID + gyi * NGW + x0 + xl; // %4 == 0
        *reinterpret_cast<float4*>(out + base) = conf4;              // tconf
        float4* tb = reinterpret_cast<float4*>(out + NBC) + base;    // tbox
        tb[0] = box[0]; tb[1] = box[1]; tb[2] = box[2]; tb[3] = box[3];
        *reinterpret_cast<float4*>(out + NBC * 5 + base) = tid4;     // tid
    }
}

extern "C" void kernel_launch(void* const* d_in, const int* in_sizes, int n_in,
                              void* d_out, int out_size)
{
    // d_in[0]=p_cat (unused, shape-only), d_in[1]=targets, d_in[2]=anchors,
    // d_in[3,4]=img_w/h (fixed 1088x608; stride hardcoded = 8)
    const float* targets = (const float*)d_in[1];
    const float* anchors = (const float*)d_in[2];
    float* out = (float*)d_out;

    dim3 grid(8, NANCH, NBATCH);   // (2 x-tiles * 4 y-tiles, 4, 16) = 512 blocks
    assign_kernel<<<grid, TPB>>>(targets, anchors, out);
}

// round 7
// speedup vs baseline: 6.3858x; 1.1379x over previous
#include <cuda_runtime.h>

// Fixed problem shapes (per setup_inputs)
constexpr int NBATCH = 16;
constexpr int NANCH  = 4;
constexpr int NT     = 64;
constexpr int NGH    = 76;
constexpr int NGW    = 136;
constexpr int GRID   = NGH * NGW;        // 10336
constexpr int CELLS  = NANCH * GRID;     // 41344
constexpr int NBC    = NBATCH * CELLS;   // 661504

// stride = 1088/136 = 8.0 exactly
constexpr float INV_STRIDE = 0.125f;

constexpr int TPB = 352;                 // 11 warps; >= QUADS: one quad/thread
constexpr int WX  = 68;                  // x-tile width  (136 = 2*68)
constexpr int QPR = WX / 4;              // 17 quads per row
constexpr int YT  = 19;                  // rows per y-tile (76 = 4*19)
constexpr int QUADS = QPR * YT;          // 323 quads per block
constexpr int NROWU = YT * 2;            // row ballot units (38)
constexpr int NCOLU = QPR * 2;           // col ballot units (34)

__global__ __launch_bounds__(TPB) void assign_kernel(
    const float* __restrict__ targets,
    const float* __restrict__ anchors,
    float* __restrict__ out)
{
    // ~7.3 KB static shared
    __shared__ float    sdyq[YT * NT];   // dy * (1/s) per (row, t)
    __shared__ unsigned smrow[NROWU];    // per-row active mask (dy > 0)
    __shared__ unsigned smcol[NCOLU];    // per-x-quad active mask (dx > 0 somewhere)
    __shared__ float sxlo[NT], sxhi[NT]; // target x extents
    __shared__ float sS[NT];             // s = a1 + a2 (reference add order)
    __shared__ float sgx[NT], sgy[NT], sgw[NT], sgh[NT], stid[NT];

    const int xt = blockIdx.x & 1;       // 0..1
    const int yt = blockIdx.x >> 1;      // 0..3
    const int a  = blockIdx.y;
    const int b  = blockIdx.z;
    const int tx = threadIdx.x;
    const int x0 = xt * WX;
    const int y0 = yt * YT;

    const float aw  = __ldg(&anchors[2 * a])     * INV_STRIDE;
    const float ah  = __ldg(&anchors[2 * a + 1]) * INV_STRIDE;
    const float aw2 = aw * 0.5f;
    const float ah2 = ah * 0.5f;
    const float a1  = aw * ah;

    // ---- phase 1: per-target preprocessing ----
    if (tx < NT) {
        const float* t = targets + (b * NT + tx) * 6;
        float gx = fminf(fmaxf(t[2] * (float)NGW, 0.0f), (float)NGW - 1.0f);
        float gy = fminf(fmaxf(t[3] * (float)NGH, 0.0f), (float)NGH - 1.0f);
        float gw = t[4] * (float)NGW;
        float gh = t[5] * (float)NGH;
        sgx[tx] = gx; sgy[tx] = gy; sgw[tx] = gw; sgh[tx] = gh;
        sxlo[tx] = gx - gw * 0.5f;
        sxhi[tx] = gx + gw * 0.5f;
        sS[tx]   = a1 + gw * gh;
        stid[tx] = t[1];
    }
    __syncthreads();

    // ---- phase 2: ballot-built sparsity masks (row: dy>0, col: dx>0) ----
    // Pruned (t) have key == 0 at every cell of the quad; all-zero-key cells
    // are winner-independent (exact epilogue recompute -> iou=0 -> conf=0,
    // box=0, tid=-1). Bit iteration ascends in t, preserving argmax
    // first-max tie order for positive keys.
    {
        const int warp = tx >> 5;
        const int lane = tx & 31;
        const float rs = __fdiv_rn(1.0f, sS[lane])        // 1/s for t=lane
                       ; // (used only in row units below; recomputed per half)
        (void)rs;
        for (int p = warp; p < NROWU + NCOLU; p += TPB / 32) {
            if (p < NROWU) {
                const int row = p >> 1;
                const int t   = ((p & 1) << 5) | lane;
                const float fpy = (float)(y0 + row);
                float hi = fminf(fpy + ah2, sgy[t] + sgh[t] * 0.5f);
                float lo = fmaxf(fpy - ah2, sgy[t] - sgh[t] * 0.5f);
                float d  = hi - lo;
                sdyq[row * NT + t] = d * __fdiv_rn(1.0f, sS[t]);
                unsigned m = __ballot_sync(0xffffffffu, d > 0.0f);
                if (lane == 0) smrow[p] = m;
            } else {
                const int pc = p - NROWU;
                const int xq = pc >> 1;
                const int t  = ((pc & 1) << 5) | lane;
                const float q0 = (float)(x0 + xq * 4);     // first px of quad
                // dx > 0 at some px in {q0..q0+3}  <=>
                //   q0+3 > xlo - aw2  AND  q0 < xhi + aw2
                bool act = (q0 + 3.0f > sxlo[t] - aw2) && (q0 < sxhi[t] + aw2);
                unsigned m = __ballot_sync(0xffffffffu, act);
                if (lane == 0) smcol[pc] = m;
            }
        }
    }
    __syncthreads();

    // ---- main: exactly one x-quad per thread ----
    if (tx < QUADS) {
        const int row = tx / QPR;
        const int xq  = tx - row * QPR;
        const int xl  = xq * 4;
        const int gyi = y0 + row;

        const float* dyqr = &sdyq[row * NT];
        const float px0 = (float)(x0 + xl);
        const float pp0 = px0 + aw2, pm0 = px0 - aw2;

        // argmax_t of key = dx_t * (dy_t / s_t)  (== argmax iou per target)
        float bk0 = 0.0f, bk1 = 0.0f, bk2 = 0.0f, bk3 = 0.0f;
        int   bt0 = 0,    bt1 = 0,    bt2 = 0,    bt3 = 0;

        unsigned m0 = smrow[row * 2]     & smcol[xq * 2];
        unsigned m1 = smrow[row * 2 + 1] & smcol[xq * 2 + 1];

        #pragma unroll 1
        for (int h = 0; h < 2; h++) {
            unsigned m = h ? m1 : m0;
            const int tbase = h ? 32 : 0;
            while (m) {
                const int t = (__ffs(m) - 1) + tbase;  m &= m - 1;
                const float xlo = sxlo[t], xhi = sxhi[t];
                const float dq  = dyqr[t];
                float d0 = fmaxf(fminf(pp0,      xhi) - fmaxf(pm0,      xlo), 0.0f);
                float d1 = fmaxf(fminf(pp0+1.0f, xhi) - fmaxf(pm0+1.0f, xlo), 0.0f);
                float d2 = fmaxf(fminf(pp0+2.0f, xhi) - fmaxf(pm0+2.0f, xlo), 0.0f);
                float d3 = fmaxf(fminf(pp0+3.0f, xhi) - fmaxf(pm0+3.0f, xlo), 0.0f);
                float k0 = d0 * dq, k1 = d1 * dq, k2 = d2 * dq, k3 = d3 * dq;
                if (k0 > bk0) { bk0 = k0; bt0 = t; }
                if (k1 > bk1) { bk1 = k1; bt1 = t; }
                if (k2 > bk2) { bk2 = k2; bt2 = t; }
                if (k3 > bk3) { bk3 = k3; bt3 = t; }
            }
        }

        // ---- epilogue: exact recompute of inter & iou for each winner ----
        const float py = (float)gyi;
        int bt[4] = {bt0, bt1, bt2, bt3};
        float4 conf4, tid4;
        float4 box[4];
        float* confp = &conf4.x;
        float* tidp  = &tid4.x;

        #pragma unroll
        for (int j = 0; j < 4; j++) {
            const int t = bt[j];
            const float gx = sgx[t], gy = sgy[t], gw = sgw[t], gh = sgh[t];
            const float s  = sS[t];
            const float pxf = px0 + (float)j;
            float dx  = fmaxf(fminf(pxf + aw2, gx + gw * 0.5f)
                            - fmaxf(pxf - aw2, gx - gw * 0.5f), 0.0f);
            float dyv = fmaxf(fminf(py + ah2, gy + gh * 0.5f)
                            - fmaxf(py - ah2, gy - gh * 0.5f), 0.0f);
            float inter = dx * dyv;
            float iou = __fdiv_rn(inter, (s - inter) + 1e-16f);

            const bool fg = iou > 0.5f;
            confp[j] = fg ? 1.0f : ((iou > 0.4f && iou < 0.5f) ? -1.0f : 0.0f);

            float4 bx = make_float4(0.0f, 0.0f, 0.0f, 0.0f);
            float tv = -1.0f;
            if (fg) {
                bx.x = __fdiv_rn(gx - pxf, aw);
                bx.y = __fdiv_rn(gy - py,  ah);
                bx.z = logf(__fdiv_rn(gw, aw));
                bx.w = logf(__fdiv_rn(gh, ah));
                tv   = stid[t];
                // has_fg in the reference is a no-op (fg implies any(fg)).
            }
            box[j] = bx;
            tidp[j] = tv;
        }

        const int base = b * CELLS + a * GRID + gyi * NGW + x0 + xl; // %4 == 0
        *reinterpret_cast<float4*>(out + base) = conf4;              // tconf
        float4* tb = reinterpret_cast<float4*>(out + NBC) + base;    // tbox
        tb[0] = box[0]; tb[1] = box[1]; tb[2] = box[2]; tb[3] = box[3];
        *reinterpret_cast<float4*>(out + NBC * 5 + base) = tid4;     // tid
    }
}

extern "C" void kernel_launch(void* const* d_in, const int* in_sizes, int n_in,
                              void* d_out, int out_size)
{
    // d_in[0]=p_cat (unused, shape-only), d_in[1]=targets, d_in[2]=anchors,
    // d_in[3,4]=img_w/h (fixed 1088x608; stride hardcoded = 8)
    const float* targets = (const float*)d_in[1];
    const float* anchors = (const float*)d_in[2];
    float* out = (float*)d_out;

    dim3 grid(8, NANCH, NBATCH);   // (2 x-tiles * 4 y-tiles, 4, 16) = 512 blocks
    assign_kernel<<<grid, TPB>>>(targets, anchors, out);
}